// round 7
// baseline (speedup 1.0000x reference)
#include <cuda_runtime.h>
#include <cuda_bf16.h>
#include <math.h>

// Problem constants (B=8, L=12288)
#define BB 8
#define LL 12288

// ---------------- scratch (no allocations allowed) ----------------
__device__ float g_numer[BB * LL];   // sum_li mask*adj*predicts[b][li], per (b, lj)
__device__ float g_counts[LL];       // sum_li mask[:, lj]
__device__ float g_sumsq[BB];        // per-batch squared norm accumulators
__device__ int   g_esize;            // detected mask element size: 1, 2, or 4 bytes

// ---------------- K_detect: infer mask dtype element size ----------------
// Truth is "element != 0" for u8/bf16/i32/f32 — only element SIZE matters.
// Scan 1M uint32 words (4 MB; smallest candidate buffer is 151 MB, safe).
//   word == 0x3F800000                        -> f32 (1.0f)  [unless bf16 evidence]
//   halves in {0, 0x3F80}, asymmetric         -> bf16
//   bytes in {0,1} with value > 1             -> u8 (one at byte pos 1..3)
//   only {0,1} words seen                     -> i32 (default es=4)
__global__ void detect_kernel(const unsigned int* __restrict__ w) {
    __shared__ int s_multi, s_f32, s_bf16;
    if (threadIdx.x == 0) { s_multi = 0; s_f32 = 0; s_bf16 = 0; }
    __syncthreads();
    const int N = 1 << 20;
    int multi = 0, f32 = 0, bf16 = 0;
    for (int i = threadIdx.x; i < N; i += blockDim.x) {
        unsigned int v = w[i];
        if (v == 0u) continue;
        if (v == 0x3F800000u) { f32 = 1; continue; }   // (also bf16 pair (0,1) — bf16 wins via other words)
        unsigned lo = v & 0xFFFFu, hi = v >> 16;
        if ((lo == 0u || lo == 0x3F80u) && (hi == 0u || hi == 0x3F80u)) { bf16 = 1; continue; }
        bool bytes_ok = true;
        #pragma unroll
        for (int b = 0; b < 4; b++) { if (((v >> (8 * b)) & 0xFFu) > 1u) bytes_ok = false; }
        if (bytes_ok && v > 1u) multi = 1;
        // v == 1 is ambiguous (i32 one vs u8 lowest-byte one) — ignore
    }
    if (multi) atomicExch(&s_multi, 1);
    if (f32)   atomicExch(&s_f32, 1);
    if (bf16)  atomicExch(&s_bf16, 1);
    __syncthreads();
    if (threadIdx.x == 0) {
        int e;
        if (s_bf16)       e = 2;
        else if (s_f32)   e = 4;
        else if (s_multi) e = 1;
        else              e = 4;   // i32
        g_esize = e;
    }
}

// ---------------- K0: zero scratch ----------------
__global__ void zero_kernel() {
    int idx = blockIdx.x * blockDim.x + threadIdx.x;
    int total = BB * LL + LL + BB;
    for (int i = idx; i < total; i += gridDim.x * blockDim.x) {
        if (i < BB * LL)            g_numer[i] = 0.0f;
        else if (i < BB * LL + LL)  g_counts[i - BB * LL] = 0.0f;
        else                        g_sumsq[i - BB * LL - LL] = 0.0f;
    }
}

// ---------------- K1: sparse masked accumulate ----------------
#define TPB 256
#define NCHUNK 32
#define CHUNK (LL / NCHUNK)   // 384

template<int ES>
__device__ __forceinline__ void accum_body(
    const float* __restrict__ predicts,
    const float* __restrict__ adj,
    const char*  __restrict__ mask)
{
    const int lj0 = blockIdx.x * (TPB * 4) + threadIdx.x * 4;
    const int li0 = blockIdx.y * CHUNK;

    float acc[BB][4];
    float cnt[4];
    #pragma unroll
    for (int b = 0; b < BB; b++)
        #pragma unroll
        for (int j = 0; j < 4; j++) acc[b][j] = 0.0f;
    #pragma unroll
    for (int j = 0; j < 4; j++) cnt[j] = 0.0f;

    #pragma unroll 4
    for (int li = li0; li < li0 + CHUNK; ++li) {
        const size_t base = (size_t)li * LL + lj0;   // element index of this thread's 4 lj
        unsigned mj = 0;                              // 4-bit nonzero map
        if (ES == 1) {
            unsigned v = *reinterpret_cast<const unsigned*>(mask + base);
            mj = ((v & 0xFFu)       ? 1u : 0u) | ((v & 0xFF00u)     ? 2u : 0u)
               | ((v & 0xFF0000u)   ? 4u : 0u) | ((v & 0xFF000000u) ? 8u : 0u);
        } else if (ES == 2) {
            uint2 v = *reinterpret_cast<const uint2*>(mask + base * 2);
            mj = ((v.x & 0xFFFFu) ? 1u : 0u) | ((v.x >> 16) ? 2u : 0u)
               | ((v.y & 0xFFFFu) ? 4u : 0u) | ((v.y >> 16) ? 8u : 0u);
        } else {
            uint4 v = *reinterpret_cast<const uint4*>(mask + base * 4);
            mj = (v.x ? 1u : 0u) | (v.y ? 2u : 0u) | (v.z ? 4u : 0u) | (v.w ? 8u : 0u);
        }
        if (mj) {
            float p[BB];
            #pragma unroll
            for (int b = 0; b < BB; b++)
                p[b] = __ldg(&predicts[b * LL + li]);   // uniform address: L1 broadcast
            #pragma unroll
            for (int j = 0; j < 4; j++) {
                if ((mj >> j) & 1u) {
                    float a = __ldg(&adj[base + j]);
                    cnt[j] += 1.0f;
                    #pragma unroll
                    for (int b = 0; b < BB; b++)
                        acc[b][j] += a * p[b];
                }
            }
        }
    }

    #pragma unroll
    for (int j = 0; j < 4; j++) {
        atomicAdd(&g_counts[lj0 + j], cnt[j]);
        #pragma unroll
        for (int b = 0; b < BB; b++)
            atomicAdd(&g_numer[b * LL + lj0 + j], acc[b][j]);
    }
}

__global__ __launch_bounds__(TPB) void accum_kernel(
    const float* __restrict__ predicts,
    const float* __restrict__ adj,
    const char*  __restrict__ mask)
{
    const int es = g_esize;   // uniform branch
    if (es == 1)      accum_body<1>(predicts, adj, mask);
    else if (es == 2) accum_body<2>(predicts, adj, mask);
    else              accum_body<4>(predicts, adj, mask);
}

// ---------------- K2: finalize candidates, diff, squared norms ----------------
__device__ __forceinline__ bool mask_nonzero(const char* mask, size_t idx, int es) {
    if (es == 1) return reinterpret_cast<const unsigned char*>(mask)[idx] != 0;
    if (es == 2) return reinterpret_cast<const unsigned short*>(mask)[idx] != 0;
    return reinterpret_cast<const unsigned int*>(mask)[idx] != 0u;
}

__global__ __launch_bounds__(256) void finalize_kernel(
    const float* __restrict__ predicts,
    const float* __restrict__ similarities,
    const char*  __restrict__ mask)
{
    __shared__ float s_sim[BB * BB];
    if (threadIdx.x < BB * BB) s_sim[threadIdx.x] = similarities[threadIdx.x];
    __syncthreads();

    const int es = g_esize;
    const int lj = blockIdx.x * blockDim.x + threadIdx.x;

    float cand[BB];
    float p_here[BB];
    float dm = mask_nonzero(mask, (size_t)lj * LL + lj, es) ? 1.0f : 0.0f;
    float inv = 1.0f / (g_counts[lj] + (1.0f - dm));
    #pragma unroll
    for (int b = 0; b < BB; b++) {
        p_here[b] = predicts[b * LL + lj];
        cand[b] = (g_numer[b * LL + lj] + (1.0f - dm) * p_here[b]) * inv;
    }

    #pragma unroll
    for (int b = 0; b < BB; b++) {
        float d = p_here[b];
        #pragma unroll
        for (int b2 = 0; b2 < BB; b2++)
            d -= s_sim[b * BB + b2] * cand[b2];
        float v = d * d;
        #pragma unroll
        for (int off = 16; off > 0; off >>= 1)
            v += __shfl_down_sync(0xFFFFFFFFu, v, off);
        if ((threadIdx.x & 31) == 0)
            atomicAdd(&g_sumsq[b], v);
    }
}

// ---------------- K3: scalar epilogue ----------------
__global__ void final_kernel(const float* __restrict__ similarities,
                             float* __restrict__ out)
{
    if (threadIdx.x == 0 && blockIdx.x == 0) {
        float total = 0.0f, cnt = 0.0f;
        for (int b = 0; b < BB; b++) {
            float rs = 0.0f;
            for (int j = 0; j < BB; j++) rs += similarities[b * BB + j];
            if (rs != 0.0f) {
                cnt += 1.0f;
                total += sqrtf(g_sumsq[b]);
            }
        }
        out[0] = (cnt == 0.0f) ? 0.0f : (total / fmaxf(cnt, 1.0f));
    }
}

// ---------------- launch ----------------
extern "C" void kernel_launch(void* const* d_in, const int* in_sizes, int n_in,
                              void* d_out, int out_size)
{
    const float* predicts = (const float*)d_in[0];
    const float* sim      = (const float*)d_in[1];
    const float* adj      = (const float*)d_in[2];
    const char*  mask     = (const char*)d_in[3];
    float* out = (float*)d_out;

    (void)in_sizes; (void)n_in; (void)out_size;

    detect_kernel<<<1, 256>>>((const unsigned int*)mask);
    zero_kernel<<<(BB * LL + LL + BB + 255) / 256, 256>>>();

    dim3 grid1(LL / (TPB * 4), NCHUNK);
    accum_kernel<<<grid1, TPB>>>(predicts, adj, mask);

    finalize_kernel<<<LL / 256, 256>>>(predicts, sim, mask);
    final_kernel<<<1, 32>>>(sim, out);
}

// round 8
// speedup vs baseline: 8.0009x; 8.0009x over previous
#include <cuda_runtime.h>
#include <cuda_bf16.h>
#include <math.h>

#define BB 8
#define LL 12288

// ---------------- scratch (no allocations allowed) ----------------
__device__ float g_numer[BB * LL];
__device__ float g_counts[LL];
__device__ float g_sumsq[BB];
__device__ int   g_esize;     // mask element size: 1, 2, 4
__device__ unsigned g_flags;  // bit0=u8-evidence, bit1=f32, bit2=bf16

// ---------------- K_init: zero detection flags ----------------
__global__ void init_kernel() { g_flags = 0u; }

// ---------------- K_detect: infer mask dtype element size (parallel) ----------------
// Truth is "element != 0"; only element SIZE matters.
//   word == 0x3F800000                  -> f32 evidence
//   halves in {0, 0x3F80}, asymmetric   -> bf16 evidence
//   bytes in {0,1} with word > 1        -> u8 evidence (one at byte pos 1..3)
//   only {0,1} words                    -> i32 (default es=4)
__global__ void detect_kernel(const unsigned int* __restrict__ w) {
    const int N = 1 << 20;  // 4 MB scan; smallest candidate buffer is 151 MB
    unsigned f = 0;
    for (int i = blockIdx.x * blockDim.x + threadIdx.x; i < N;
         i += gridDim.x * blockDim.x) {
        unsigned v = w[i];
        if (v == 0u) continue;
        if (v == 0x3F800000u) { f |= 2u; continue; }
        unsigned lo = v & 0xFFFFu, hi = v >> 16;
        if ((lo == 0u || lo == 0x3F80u) && (hi == 0u || hi == 0x3F80u)) { f |= 4u; continue; }
        bool bytes_ok = true;
        #pragma unroll
        for (int b = 0; b < 4; b++) { if (((v >> (8 * b)) & 0xFFu) > 1u) bytes_ok = false; }
        if (bytes_ok && v > 1u) f |= 1u;
    }
    // warp-reduce then one atomic per warp
    #pragma unroll
    for (int off = 16; off > 0; off >>= 1)
        f |= __shfl_xor_sync(0xFFFFFFFFu, f, off);
    if ((threadIdx.x & 31) == 0 && f) atomicOr(&g_flags, f);
}

// ---------------- K0: zero scratch + resolve esize ----------------
__global__ void zero_kernel() {
    if (blockIdx.x == 0 && threadIdx.x == 0) {
        unsigned f = g_flags;
        int e;
        if (f & 4u)      e = 2;   // bf16
        else if (f & 2u) e = 4;   // f32
        else if (f & 1u) e = 1;   // u8
        else             e = 4;   // i32
        g_esize = e;
    }
    int idx = blockIdx.x * blockDim.x + threadIdx.x;
    int total = BB * LL + LL + BB;
    for (int i = idx; i < total; i += gridDim.x * blockDim.x) {
        if (i < BB * LL)            g_numer[i] = 0.0f;
        else if (i < BB * LL + LL)  g_counts[i - BB * LL] = 0.0f;
        else                        g_sumsq[i - BB * LL - LL] = 0.0f;
    }
}

// ---------------- K1: sparse masked accumulate ----------------
#define TPB 256
#define NCHUNK 32
#define CHUNK (LL / NCHUNK)   // 384
#define UROW 4                // mask rows prefetched per batch (MLP)

template<int ES>
__device__ __forceinline__ void accum_body(
    const float* __restrict__ predicts,
    const float* __restrict__ adj,
    const char*  __restrict__ mask)
{
    __shared__ float s_pred[BB * CHUNK];   // 12 KB: predicts slice for this li-chunk
    const int li0 = blockIdx.y * CHUNK;
    for (int i = threadIdx.x; i < BB * CHUNK; i += TPB) {
        int b = i / CHUNK, li = i % CHUNK;
        s_pred[i] = predicts[b * LL + li0 + li];
    }
    __syncthreads();

    const int lj0 = blockIdx.x * (TPB * 4) + threadIdx.x * 4;

    float acc[BB][4];
    float cnt[4];
    #pragma unroll
    for (int b = 0; b < BB; b++)
        #pragma unroll
        for (int j = 0; j < 4; j++) acc[b][j] = 0.0f;
    #pragma unroll
    for (int j = 0; j < 4; j++) cnt[j] = 0.0f;

    for (int li = li0; li < li0 + CHUNK; li += UROW) {
        unsigned mj[UROW];
        // ---- batched mask loads (independent: high MLP) ----
        if (ES == 4) {
            uint4 v[UROW];
            #pragma unroll
            for (int u = 0; u < UROW; u++)
                v[u] = *reinterpret_cast<const uint4*>(
                    mask + ((size_t)(li + u) * LL + lj0) * 4);
            #pragma unroll
            for (int u = 0; u < UROW; u++)
                mj[u] = (v[u].x ? 1u : 0u) | (v[u].y ? 2u : 0u)
                      | (v[u].z ? 4u : 0u) | (v[u].w ? 8u : 0u);
        } else if (ES == 2) {
            uint2 v[UROW];
            #pragma unroll
            for (int u = 0; u < UROW; u++)
                v[u] = *reinterpret_cast<const uint2*>(
                    mask + ((size_t)(li + u) * LL + lj0) * 2);
            #pragma unroll
            for (int u = 0; u < UROW; u++)
                mj[u] = ((v[u].x & 0xFFFFu) ? 1u : 0u) | ((v[u].x >> 16) ? 2u : 0u)
                      | ((v[u].y & 0xFFFFu) ? 4u : 0u) | ((v[u].y >> 16) ? 8u : 0u);
        } else {
            unsigned v[UROW];
            #pragma unroll
            for (int u = 0; u < UROW; u++)
                v[u] = *reinterpret_cast<const unsigned*>(
                    mask + (size_t)(li + u) * LL + lj0);
            #pragma unroll
            for (int u = 0; u < UROW; u++)
                mj[u] = ((v[u] & 0xFFu)       ? 1u : 0u) | ((v[u] & 0xFF00u)     ? 2u : 0u)
                      | ((v[u] & 0xFF0000u)   ? 4u : 0u) | ((v[u] & 0xFF000000u) ? 8u : 0u);
        }
        // ---- sparse processing ----
        #pragma unroll
        for (int u = 0; u < UROW; u++) {
            if (mj[u]) {
                const int lofs = li - li0 + u;
                float p[BB];
                #pragma unroll
                for (int b = 0; b < BB; b++)
                    p[b] = s_pred[b * CHUNK + lofs];   // smem broadcast
                const size_t base = (size_t)(li + u) * LL + lj0;
                #pragma unroll
                for (int j = 0; j < 4; j++) {
                    if ((mj[u] >> j) & 1u) {
                        float a = __ldg(&adj[base + j]);
                        cnt[j] += 1.0f;
                        #pragma unroll
                        for (int b = 0; b < BB; b++)
                            acc[b][j] += a * p[b];
                    }
                }
            }
        }
    }

    #pragma unroll
    for (int j = 0; j < 4; j++) {
        atomicAdd(&g_counts[lj0 + j], cnt[j]);
        #pragma unroll
        for (int b = 0; b < BB; b++)
            atomicAdd(&g_numer[b * LL + lj0 + j], acc[b][j]);
    }
}

__global__ __launch_bounds__(TPB) void accum_kernel(
    const float* __restrict__ predicts,
    const float* __restrict__ adj,
    const char*  __restrict__ mask)
{
    const int es = g_esize;   // uniform
    if (es == 1)      accum_body<1>(predicts, adj, mask);
    else if (es == 2) accum_body<2>(predicts, adj, mask);
    else              accum_body<4>(predicts, adj, mask);
}

// ---------------- K2: finalize candidates, diff, squared norms ----------------
__device__ __forceinline__ bool mask_nonzero(const char* mask, size_t idx, int es) {
    if (es == 1) return reinterpret_cast<const unsigned char*>(mask)[idx] != 0;
    if (es == 2) return reinterpret_cast<const unsigned short*>(mask)[idx] != 0;
    return reinterpret_cast<const unsigned int*>(mask)[idx] != 0u;
}

__global__ __launch_bounds__(256) void finalize_kernel(
    const float* __restrict__ predicts,
    const float* __restrict__ similarities,
    const char*  __restrict__ mask)
{
    __shared__ float s_sim[BB * BB];
    if (threadIdx.x < BB * BB) s_sim[threadIdx.x] = similarities[threadIdx.x];
    __syncthreads();

    const int es = g_esize;
    const int lj = blockIdx.x * blockDim.x + threadIdx.x;

    float cand[BB];
    float p_here[BB];
    float dm = mask_nonzero(mask, (size_t)lj * LL + lj, es) ? 1.0f : 0.0f;
    float inv = 1.0f / (g_counts[lj] + (1.0f - dm));
    #pragma unroll
    for (int b = 0; b < BB; b++) {
        p_here[b] = predicts[b * LL + lj];
        cand[b] = (g_numer[b * LL + lj] + (1.0f - dm) * p_here[b]) * inv;
    }

    #pragma unroll
    for (int b = 0; b < BB; b++) {
        float d = p_here[b];
        #pragma unroll
        for (int b2 = 0; b2 < BB; b2++)
            d -= s_sim[b * BB + b2] * cand[b2];
        float v = d * d;
        #pragma unroll
        for (int off = 16; off > 0; off >>= 1)
            v += __shfl_down_sync(0xFFFFFFFFu, v, off);
        if ((threadIdx.x & 31) == 0)
            atomicAdd(&g_sumsq[b], v);
    }
}

// ---------------- K3: scalar epilogue ----------------
__global__ void final_kernel(const float* __restrict__ similarities,
                             float* __restrict__ out)
{
    if (threadIdx.x == 0 && blockIdx.x == 0) {
        float total = 0.0f, cnt = 0.0f;
        for (int b = 0; b < BB; b++) {
            float rs = 0.0f;
            for (int j = 0; j < BB; j++) rs += similarities[b * BB + j];
            if (rs != 0.0f) {
                cnt += 1.0f;
                total += sqrtf(g_sumsq[b]);
            }
        }
        out[0] = (cnt == 0.0f) ? 0.0f : (total / fmaxf(cnt, 1.0f));
    }
}

// ---------------- launch ----------------
extern "C" void kernel_launch(void* const* d_in, const int* in_sizes, int n_in,
                              void* d_out, int out_size)
{
    const float* predicts = (const float*)d_in[0];
    const float* sim      = (const float*)d_in[1];
    const float* adj      = (const float*)d_in[2];
    const char*  mask     = (const char*)d_in[3];
    float* out = (float*)d_out;

    (void)in_sizes; (void)n_in; (void)out_size;

    init_kernel<<<1, 1>>>();
    detect_kernel<<<64, 256>>>((const unsigned int*)mask);
    zero_kernel<<<(BB * LL + LL + BB + 255) / 256, 256>>>();

    dim3 grid1(LL / (TPB * 4), NCHUNK);
    accum_kernel<<<grid1, TPB>>>(predicts, adj, mask);

    finalize_kernel<<<LL / 256, 256>>>(predicts, sim, mask);
    final_kernel<<<1, 32>>>(sim, out);
}

// round 10
// speedup vs baseline: 9.2643x; 1.1579x over previous
#include <cuda_runtime.h>
#include <cuda_bf16.h>
#include <math.h>

#define BB 8
#define LL 12288

// ---------------- scratch (no allocations allowed) ----------------
__device__ float g_numer[BB * LL];
__device__ float g_counts[LL];
__device__ float g_sumsq[BB];
__device__ unsigned g_flags = 0u;  // bit0=u8, bit1=f32, bit2=bf16 (reset by finalize last block)
__device__ int g_done = 0;         // finalize completion counter (self-resetting)

__device__ __forceinline__ int resolve_es(unsigned f) {
    if (f & 4u) return 2;   // bf16
    if (f & 2u) return 4;   // f32
    if (f & 1u) return 1;   // u8
    return 4;               // i32
}

// ---------------- K_prep: zero scratch + parallel dtype scan ----------------
// Truth is "element != 0"; only element SIZE matters.
__global__ __launch_bounds__(256) void prep_kernel(const unsigned int* __restrict__ w) {
    const int gid = blockIdx.x * blockDim.x + threadIdx.x;
    const int gsz = gridDim.x * blockDim.x;

    // zero scratch
    const int total = BB * LL + LL + BB;
    for (int i = gid; i < total; i += gsz) {
        if (i < BB * LL)            g_numer[i] = 0.0f;
        else if (i < BB * LL + LL)  g_counts[i - BB * LL] = 0.0f;
        else                        g_sumsq[i - BB * LL - LL] = 0.0f;
    }

    // dtype evidence scan over first 4 MB of mask (smallest candidate is 151 MB)
    const int N = 1 << 20;
    unsigned f = 0;
    for (int i = gid; i < N; i += gsz) {
        unsigned v = w[i];
        if (v == 0u) continue;
        if (v == 0x3F800000u) { f |= 2u; continue; }           // f32 1.0
        unsigned lo = v & 0xFFFFu, hi = v >> 16;
        if ((lo == 0u || lo == 0x3F80u) && (hi == 0u || hi == 0x3F80u)) { f |= 4u; continue; } // bf16
        bool bytes_ok = true;
        #pragma unroll
        for (int b = 0; b < 4; b++) { if (((v >> (8 * b)) & 0xFFu) > 1u) bytes_ok = false; }
        if (bytes_ok && v > 1u) f |= 1u;                       // u8 one at byte pos 1..3
    }
    #pragma unroll
    for (int off = 16; off > 0; off >>= 1)
        f |= __shfl_xor_sync(0xFFFFFFFFu, f, off);
    if ((threadIdx.x & 31) == 0 && f) atomicOr(&g_flags, f);
}

// ---------------- K1: sparse masked accumulate (pipelined) ----------------
#define TPB 256
#define NCHUNK 48
#define CHUNK (LL / NCHUNK)   // 256
#define UROW 2                // rows per pipelined batch

template<int ES>
__device__ __forceinline__ void accum_body(
    const float* __restrict__ predicts,
    const float* __restrict__ adj,
    const char*  __restrict__ mask)
{
    __shared__ float s_pred[BB * CHUNK];   // 8 KB
    const int li0 = blockIdx.y * CHUNK;
    for (int i = threadIdx.x; i < BB * CHUNK; i += TPB) {
        int b = i / CHUNK, li = i % CHUNK;
        s_pred[i] = predicts[b * LL + li0 + li];
    }
    __syncthreads();

    const int lj0 = blockIdx.x * (TPB * 4) + threadIdx.x * 4;

    float acc[BB][4];
    float cnt[4];
    #pragma unroll
    for (int b = 0; b < BB; b++)
        #pragma unroll
        for (int j = 0; j < 4; j++) acc[b][j] = 0.0f;
    #pragma unroll
    for (int j = 0; j < 4; j++) cnt[j] = 0.0f;

    // vector type per element size
    typedef typename std::conditional<ES == 4, uint4,
            typename std::conditional<ES == 2, uint2, unsigned>::type>::type VecT;

    auto loadrow = [&](int li) -> VecT {
        return *reinterpret_cast<const VecT*>(mask + ((size_t)li * LL + lj0) * ES);
    };
    auto rowbits = [&](VecT v) -> unsigned {
        if (ES == 4) {
            const uint4& u = reinterpret_cast<const uint4&>(v);
            return (u.x ? 1u : 0u) | (u.y ? 2u : 0u) | (u.z ? 4u : 0u) | (u.w ? 8u : 0u);
        } else if (ES == 2) {
            const uint2& u = reinterpret_cast<const uint2&>(v);
            return ((u.x & 0xFFFFu) ? 1u : 0u) | ((u.x >> 16) ? 2u : 0u)
                 | ((u.y & 0xFFFFu) ? 4u : 0u) | ((u.y >> 16) ? 8u : 0u);
        } else {
            const unsigned& u = reinterpret_cast<const unsigned&>(v);
            return ((u & 0xFFu)     ? 1u : 0u) | ((u & 0xFF00u)     ? 2u : 0u)
                 | ((u & 0xFF0000u) ? 4u : 0u) | ((u & 0xFF000000u) ? 8u : 0u);
        }
    };

    // software pipeline: batch n+1 loads issue before batch n is processed
    VecT cur[UROW];
    #pragma unroll
    for (int u = 0; u < UROW; u++) cur[u] = loadrow(li0 + u);

    for (int li = li0; li < li0 + CHUNK; li += UROW) {
        VecT nxt[UROW];
        const bool has_next = (li + UROW) < (li0 + CHUNK);
        if (has_next) {
            #pragma unroll
            for (int u = 0; u < UROW; u++) nxt[u] = loadrow(li + UROW + u);
        }
        #pragma unroll
        for (int u = 0; u < UROW; u++) {
            unsigned mj = rowbits(cur[u]);
            if (mj) {
                const int lofs = li - li0 + u;
                float p[BB];
                #pragma unroll
                for (int b = 0; b < BB; b++)
                    p[b] = s_pred[b * CHUNK + lofs];
                const size_t base = (size_t)(li + u) * LL + lj0;
                #pragma unroll
                for (int j = 0; j < 4; j++) {
                    if ((mj >> j) & 1u) {
                        float a = __ldg(&adj[base + j]);
                        cnt[j] += 1.0f;
                        #pragma unroll
                        for (int b = 0; b < BB; b++)
                            acc[b][j] += a * p[b];
                    }
                }
            }
        }
        if (has_next) {
            #pragma unroll
            for (int u = 0; u < UROW; u++) cur[u] = nxt[u];
        }
    }

    #pragma unroll
    for (int j = 0; j < 4; j++) {
        atomicAdd(&g_counts[lj0 + j], cnt[j]);
        #pragma unroll
        for (int b = 0; b < BB; b++)
            atomicAdd(&g_numer[b * LL + lj0 + j], acc[b][j]);
    }
}

#include <type_traits>

__global__ __launch_bounds__(TPB, 4) void accum_kernel(
    const float* __restrict__ predicts,
    const float* __restrict__ adj,
    const char*  __restrict__ mask)
{
    const int es = resolve_es(g_flags);   // uniform
    if (es == 1)      accum_body<1>(predicts, adj, mask);
    else if (es == 2) accum_body<2>(predicts, adj, mask);
    else              accum_body<4>(predicts, adj, mask);
}

// ---------------- K2: finalize + fused scalar epilogue (last block) ----------------
__device__ __forceinline__ bool mask_nonzero(const char* mask, size_t idx, int es) {
    if (es == 1) return reinterpret_cast<const unsigned char*>(mask)[idx] != 0;
    if (es == 2) return reinterpret_cast<const unsigned short*>(mask)[idx] != 0;
    return reinterpret_cast<const unsigned int*>(mask)[idx] != 0u;
}

__global__ __launch_bounds__(256) void finalize_kernel(
    const float* __restrict__ predicts,
    const float* __restrict__ similarities,
    const char*  __restrict__ mask,
    float* __restrict__ out)
{
    __shared__ float s_sim[BB * BB];
    __shared__ bool s_last;
    if (threadIdx.x < BB * BB) s_sim[threadIdx.x] = similarities[threadIdx.x];
    __syncthreads();

    const int es = resolve_es(g_flags);
    const int lj = blockIdx.x * blockDim.x + threadIdx.x;

    float cand[BB];
    float p_here[BB];
    float dm = mask_nonzero(mask, (size_t)lj * LL + lj, es) ? 1.0f : 0.0f;
    float inv = 1.0f / (g_counts[lj] + (1.0f - dm));
    #pragma unroll
    for (int b = 0; b < BB; b++) {
        p_here[b] = predicts[b * LL + lj];
        cand[b] = (g_numer[b * LL + lj] + (1.0f - dm) * p_here[b]) * inv;
    }

    #pragma unroll
    for (int b = 0; b < BB; b++) {
        float d = p_here[b];
        #pragma unroll
        for (int b2 = 0; b2 < BB; b2++)
            d -= s_sim[b * BB + b2] * cand[b2];
        float v = d * d;
        #pragma unroll
        for (int off = 16; off > 0; off >>= 1)
            v += __shfl_down_sync(0xFFFFFFFFu, v, off);
        if ((threadIdx.x & 31) == 0)
            atomicAdd(&g_sumsq[b], v);
    }

    // last-block scalar epilogue
    __threadfence();
    __syncthreads();
    if (threadIdx.x == 0) {
        int t = atomicAdd(&g_done, 1);
        s_last = (t == (int)gridDim.x - 1);
    }
    __syncthreads();
    if (s_last && threadIdx.x == 0) {
        float total = 0.0f, cnt = 0.0f;
        for (int b = 0; b < BB; b++) {
            float rs = 0.0f;
            for (int j = 0; j < BB; j++) rs += s_sim[b * BB + j];
            if (rs != 0.0f) {
                cnt += 1.0f;
                total += sqrtf(*(volatile float*)&g_sumsq[b]);
            }
        }
        out[0] = (cnt == 0.0f) ? 0.0f : (total / fmaxf(cnt, 1.0f));
        g_done = 0;      // self-reset for next graph replay
        g_flags = 0u;
    }
}

// ---------------- launch ----------------
extern "C" void kernel_launch(void* const* d_in, const int* in_sizes, int n_in,
                              void* d_out, int out_size)
{
    const float* predicts = (const float*)d_in[0];
    const float* sim      = (const float*)d_in[1];
    const float* adj      = (const float*)d_in[2];
    const char*  mask     = (const char*)d_in[3];
    float* out = (float*)d_out;

    (void)in_sizes; (void)n_in; (void)out_size;

    prep_kernel<<<128, 256>>>((const unsigned int*)mask);

    dim3 grid1(LL / (TPB * 4), NCHUNK);
    accum_kernel<<<grid1, TPB>>>(predicts, adj, mask);

    finalize_kernel<<<LL / 256, 256>>>(predicts, sim, mask, out);
}